// round 11
// baseline (speedup 1.0000x reference)
#include <cuda_runtime.h>
#include <cstdint>

typedef unsigned long long u64;

#define NI 128
#define NP 2000
#define MG 100
#define NA (NP + MG)          // 2100
#define NS 512
#define MAXPOS 128
#define NUMNEG 384
#define NT 1024
#define NG 512                // threads per specialized group
#define NB 2048               // buckets
#define CHUNK 4               // 128 % CHUNK == 0 -> boundary at warp 1

#define BAR_SORT(n)  asm volatile("bar.sync 1, %0;" :: "n"(n) : "memory")
#define BAR_CLS(n)   asm volatile("bar.sync 2, %0;" :: "n"(n) : "memory")

struct __align__(16) SmemLayout {
    float4 roi[NA];           // 33600 B: [0,2000) prefetched rois, [2000,2100) gt
    u64    skey[NA];          // 16800
    int    cnt[NB];           // 8192
    int    off[NB];           // 8192
    float  sc[NA];            // 8400: [0,2000) scores, [2000,2100) = 1.0
    float4 vbox[MG];          // 1600
    float2 vaux[MG];          // 800  (area, gt-index as float bits)
    short  amax[NA];          // 4200
    unsigned char cls[NA];    // 2100 (shift: 42=pos, 21=neg-cand, 0=ignore)
    int    wcnt[4];
    int    iwsum[16];         // sort-group warp partials
    u64    wsum[32];
    u64    totals, ebound;
    int    V;
    int    next;              // work-steal box counter
    int    ready;             // vbox/V published flag
};

__device__ __forceinline__ void cp16(void* s, const void* g) {
    uint32_t sa = (uint32_t)__cvta_generic_to_shared(s);
    asm volatile("cp.async.cg.shared.global [%0], [%1], 16;" :: "r"(sa), "l"(g));
}

// Classify two boxes vs all V gt boxes. Best tracked as exact (inter, union)
// pair; cross-mult compare == exact-quotient argmax. RN division is monotone,
// so the final max IoU (threshold test) is identical to the reference.
__device__ __forceinline__ void classify_pair(SmemLayout* sm, int V, int i0, int i1) {
    float4 b0 = sm->roi[i0]; float sc0 = sm->sc[i0];
    float4 b1 = sm->roi[i1]; float sc1 = sm->sc[i1];
    float aa0 = fmaxf(b0.z - b0.x, 0.f) * fmaxf(b0.w - b0.y, 0.f);
    float aa1 = fmaxf(b1.z - b1.x, 0.f) * fmaxf(b1.w - b1.y, 0.f);
    float bi0 = 0.f, bu0 = 1.f, bi1 = 0.f, bu1 = 1.f;
    int a0 = 0, a1 = 0;
    #pragma unroll 2
    for (int m = 0; m < V; ++m) {
        float4 g  = sm->vbox[m];
        float2 ax = sm->vaux[m];
        float w0 = fminf(b0.z, g.z) - fmaxf(b0.x, g.x);
        float h0 = fminf(b0.w, g.w) - fmaxf(b0.y, g.y);
        float in0 = fmaxf(w0, 0.f) * fmaxf(h0, 0.f);   // == ref's clip product
        float un0 = (aa0 + ax.x) - in0;                // == ref's (aa+ab)-inter
        if (in0 * bu0 > bi0 * un0) { bi0 = in0; bu0 = un0; a0 = __float_as_int(ax.y); }
        float w1 = fminf(b1.z, g.z) - fmaxf(b1.x, g.x);
        float h1 = fminf(b1.w, g.w) - fmaxf(b1.y, g.y);
        float in1 = fmaxf(w1, 0.f) * fmaxf(h1, 0.f);
        float un1 = (aa1 + ax.x) - in1;
        if (in1 * bu1 > bi1 * un1) { bi1 = in1; bu1 = un1; a1 = __float_as_int(ax.y); }
    }
    float q0 = __fdiv_rn(bi0, bu0);   // IEEE div once per box: bit-match JAX max
    float q1 = __fdiv_rn(bi1, bu1);
    sm->cls[i0]  = (q0 >= 0.5f) ? 42 : ((sc0 < 0.f) ? 0 : 21);
    sm->amax[i0] = (short)a0;
    sm->cls[i1]  = (q1 >= 0.5f) ? 42 : ((sc1 < 0.f) ? 0 : 21);
    sm->amax[i1] = (short)a1;
}

__device__ __forceinline__ void classify_one(SmemLayout* sm, int V, int i0) {
    float4 b0 = sm->roi[i0]; float sc0 = sm->sc[i0];
    float aa0 = fmaxf(b0.z - b0.x, 0.f) * fmaxf(b0.w - b0.y, 0.f);
    float bi0 = 0.f, bu0 = 1.f; int a0 = 0;
    for (int m = 0; m < V; ++m) {
        float4 g  = sm->vbox[m];
        float2 ax = sm->vaux[m];
        float w0 = fminf(b0.z, g.z) - fmaxf(b0.x, g.x);
        float h0 = fminf(b0.w, g.w) - fmaxf(b0.y, g.y);
        float in0 = fmaxf(w0, 0.f) * fmaxf(h0, 0.f);
        float un0 = (aa0 + ax.x) - in0;
        if (in0 * bu0 > bi0 * un0) { bi0 = in0; bu0 = un0; a0 = __float_as_int(ax.y); }
    }
    float q0 = __fdiv_rn(bi0, bu0);
    sm->cls[i0]  = (q0 >= 0.5f) ? 42 : ((sc0 < 0.f) ? 0 : 21);
    sm->amax[i0] = (short)a0;
}

__global__ __launch_bounds__(NT)
void rcnn_sampler_kernel(const float4* __restrict__ g_rois,   // [NI, NP]
                         const float*  __restrict__ g_scores, // [NI, NP]
                         const float4* __restrict__ g_gt,     // [NI, MG]
                         const float*  __restrict__ g_rand,   // [NI, NA]
                         float* __restrict__ out)
{
    extern __shared__ char smem_raw[];
    SmemLayout* sm = reinterpret_cast<SmemLayout*>(smem_raw);

    const int img = blockIdx.x;
    const int tid = threadIdx.x;
    const unsigned int lane = tid & 31, wd = tid >> 5;

    if (tid == 0) { sm->next = 0; sm->ready = 0; }
    __syncthreads();

    if (tid < NG) {
        // ================= CLASSIFY GROUP (warps 0-15) =================
        // prefetch rois (2000 float4) + scores (2000 f32 = 500 x 16B)
        const float4* rsrc = g_rois + (size_t)img * NP;
        for (int i = tid; i < NP; i += NG) cp16(&sm->roi[i], rsrc + i);
        if (tid < NP / 4) cp16(&sm->sc[tid * 4], g_scores + (size_t)img * NP + tid * 4);
        asm volatile("cp.async.commit_group;");

        // gt load + validity. Zero-area gt gives IoU == 0.0f exactly vs every
        // box (clip algebra), so skipping is bit-exact given best=0 / arg=0.
        float4 myb; float myar = 0.f; bool myval = false;
        if (tid < MG) {
            myb = g_gt[(size_t)img * MG + tid];
            sm->roi[NP + tid] = myb;          // unify: gt appended to roi[]
            sm->sc[NP + tid]  = 1.0f;
            myar = fmaxf(myb.z - myb.x, 0.f) * fmaxf(myb.w - myb.y, 0.f);
            myval = myar > 0.f;
        }
        unsigned bal = __ballot_sync(0xFFFFFFFFu, myval);
        if (lane == 0 && wd < 4) sm->wcnt[wd] = __popc(bal);

        asm volatile("cp.async.wait_group 0;");
        BAR_CLS(NG);                           // wcnt + gt stores + prefetch visible

        if (myval) {                           // compact valid gt (order-preserving)
            int off = __popc(bal & ((1u << lane) - 1));
            for (int w = 0; w < (int)wd; ++w) off += sm->wcnt[w];
            sm->vbox[off] = myb;
            sm->vaux[off] = make_float2(myar, __int_as_float(tid));
        }
        if (tid == 0) sm->V = sm->wcnt[0] + sm->wcnt[1] + sm->wcnt[2] + sm->wcnt[3];
        BAR_CLS(NG);                           // vbox/vaux/V + all box data ready
        if (tid == 0) {
            __threadfence_block();
            atomicExch(&sm->ready, 1);         // publish to sort group
        }
    } else {
        // ================= SORT GROUP (warps 16-31) =================
        const int st = tid - NG;

        // zero histogram (int4 stores)
        ((int4*)sm->cnt)[st] = make_int4(0, 0, 0, 0);

        // keys: (rand_bits << 32) | idx. rand in [0,1): positive float bit
        // pattern is order-preserving; embedded idx makes ties stable, so
        // sorting these u64s == jnp.argsort(rand) exactly.
        u64 myk[5]; int mybkt[5]; int nown = 0;
        const float* rp = g_rand + (size_t)img * NA;
        #pragma unroll
        for (int e = 0; e < 5; ++e) {
            int i = st + e * NG;
            if (i < NA) {
                float r = rp[i];
                myk[e] = ((u64)__float_as_uint(r) << 32) | (unsigned int)i;
                // uniform value -> order-preserving bucket (monotone fp ops)
                mybkt[e] = min((int)(r * (float)NB), NB - 1);
                ++nown;
            }
        }
        BAR_SORT(NG);                          // zeroed cnt visible

        #pragma unroll
        for (int e = 0; e < 5; ++e)
            if (e < nown) atomicAdd(&sm->cnt[mybkt[e]], 1);
        BAR_SORT(NG);

        // exclusive scan of 2048 bins: 4 consecutive bins per thread
        {
            int c0 = sm->cnt[4 * st], c1 = sm->cnt[4 * st + 1];
            int c2 = sm->cnt[4 * st + 2], c3 = sm->cnt[4 * st + 3];
            int s4 = c0 + c1 + c2 + c3;
            int vv = s4;
            #pragma unroll
            for (int o = 1; o < 32; o <<= 1) {
                int n = __shfl_up_sync(0xFFFFFFFFu, vv, o);
                if (lane >= (unsigned)o) vv += n;
            }
            const int swd = st >> 5;           // sort-group warp 0..15
            if (lane == 31) sm->iwsum[swd] = vv;
            BAR_SORT(NG);
            if (st < 32) {                     // first sort warp scans 16 partials
                int t0 = (st < 16) ? sm->iwsum[st] : 0;
                int tv = t0;
                #pragma unroll
                for (int o = 1; o < 16; o <<= 1) {
                    int n = __shfl_up_sync(0xFFFFFFFFu, tv, o);
                    if (lane >= (unsigned)o) tv += n;
                }
                if (st < 16) sm->iwsum[st] = tv - t0;   // exclusive
            }
            BAR_SORT(NG);
            int ex = sm->iwsum[swd] + (vv - s4);
            sm->off[4 * st]     = ex;
            sm->off[4 * st + 1] = ex + c0;
            sm->off[4 * st + 2] = ex + c0 + c1;
            sm->off[4 * st + 3] = ex + c0 + c1 + c2;
        }
        BAR_SORT(NG);

        // scatter keys into bucket slots (off[b] becomes bucket END)
        #pragma unroll
        for (int e = 0; e < 5; ++e)
            if (e < nown) {
                int p = atomicAdd(&sm->off[mybkt[e]], 1);
                sm->skey[p] = myk[e];
            }
        BAR_SORT(NG);

        // per-bucket insertion sort (avg load ~1)
        for (int bb = st; bb < NB; bb += NG) {
            int end = sm->off[bb];
            int stt = end - sm->cnt[bb];
            for (int a = stt + 1; a < end; ++a) {
                u64 key = sm->skey[a];
                int p = a - 1;
                while (p >= stt && sm->skey[p] > key) { sm->skey[p + 1] = sm->skey[p]; --p; }
                sm->skey[p + 1] = key;
            }
        }

        // join the classify work pool once vbox/V are published
        while (atomicAdd(&sm->ready, 0) == 0) {}
        __threadfence_block();
    }

    // ======== shared work-steal classification (both groups) ========
    // Warp-granular chunks of 128 boxes, lane-coalesced within a chunk.
    const int V = sm->V;
    for (;;) {
        int base = 0;
        if (lane == 0) base = atomicAdd(&sm->next, 128);
        base = __shfl_sync(0xFFFFFFFFu, base, 0);
        if (base >= NA) break;
        int i = base + lane;
        if (base + 128 <= NA) {
            classify_pair(sm, V, i, i + 32);
            classify_pair(sm, V, i + 64, i + 96);
        } else {                               // final 52-box chunk
            if (i < NA)      classify_one(sm, V, i);
            if (i + 32 < NA) classify_one(sm, V, i + 32);
        }
    }

    __syncthreads();   // join: skey (sort) + cls/amax/roi (classify) all visible

    // ======== phase F: packed per-class stable-rank scan ========
    // CHUNK=4: thread t covers j in [4t, 4t+4); MAXPOS=128 boundary = warp 1
    const int j0 = tid * CHUNK;
    unsigned int idxr[CHUNK]; int shr[CHUNK];
    int nj = 0;
    u64 loc = 0;
    #pragma unroll
    for (int e = 0; e < CHUNK; ++e) {
        int j = j0 + e;
        if (j < NA) {
            unsigned int idx = (unsigned int)sm->skey[j];
            int sh = sm->cls[idx];
            idxr[e] = idx; shr[e] = sh;
            loc += 1ull << sh;
            ++nj;
        }
    }
    u64 v = loc;
    #pragma unroll
    for (int o = 1; o < 32; o <<= 1) {
        u64 n = __shfl_up_sync(0xFFFFFFFFu, v, o);
        if (lane >= (unsigned)o) v += n;
    }
    if (lane == 31) sm->wsum[wd] = v;
    __syncthreads();
    if (tid < 32) {
        u64 t0 = sm->wsum[tid];
        u64 tv = t0;
        #pragma unroll
        for (int o = 1; o < 32; o <<= 1) {
            u64 n = __shfl_up_sync(0xFFFFFFFFu, tv, o);
            if (lane >= (unsigned)o) tv += n;
        }
        sm->wsum[tid] = tv - t0;                 // exclusive
        if (tid == 1)  sm->ebound = tv - t0;     // prefix over j in [0,128)
        if (tid == 31) sm->totals = tv;          // inclusive total
    }
    __syncthreads();
    const u64 excl = sm->wsum[wd] + (v - loc);

    // ======== phase G: closed-form slot assignment + output ========
    const u64 M21 = (1ull << 21) - 1;
    const u64 tot = sm->totals, ev = sm->ebound;
    const int c3  = (int)((tot >> 42) & M21);
    const int c2t = (int)((tot >> 21) & M21);
    const int e3  = (int)((ev  >> 42) & M21);
    const int e2  = (int)((ev  >> 21) & M21);
    const int e0  = (int)( ev         & M21);
    const int d2 = c2t - e2, d3 = c3 - e3;

    int r3 = (int)((excl >> 42) & M21);
    int r2 = (int)((excl >> 21) & M21);
    int r0 = (int)( excl         & M21);

    float* out_rois    = out;
    float* out_samples = out + (size_t)NI * NS * 4;
    float* out_matches = out_samples + (size_t)NI * NS;

    #pragma unroll
    for (int e = 0; e < CHUNK; ++e) {
        if (e >= nj) break;
        const int j = j0 + e;
        unsigned int idx = idxr[e];
        int sh = shr[e];
        int r;
        if (sh == 42)      r = r3++;
        else if (sh == 21) r = r2++;
        else               r = r0++;

        // top partition: priority 3 > 2 > 0, stable in j, first MAXPOS
        int tb = (sh == 42) ? 0 : (sh == 21 ? c3 : (c3 + c2t));
        int pos = tb + r;
        int slot1 = (pos < MAXPOS) ? pos : -1;

        // bottom partition: among j>=MAXPOS, priority 2 > 3 > 0, first NUMNEG
        int slot2 = -1;
        if (j >= MAXPOS) {
            int ec = (sh == 42) ? e3 : (sh == 21 ? e2 : e0);
            int bb = (sh == 21) ? 0 : (sh == 42 ? d2 : (d2 + d3));
            int pos2 = bb + (r - ec);
            if (pos2 < NUMNEG) slot2 = MAXPOS + pos2;
        }

        if (slot1 >= 0 || slot2 >= 0) {
            float4 b = sm->roi[idx];
            float sval = (sh == 42) ? 1.f : (sh == 21 ? -1.f : 0.f);
            float mval = (float)sm->amax[idx];
            if (slot1 >= 0) {
                size_t o = (size_t)img * NS + slot1;
                ((float4*)out_rois)[o] = b;
                out_samples[o] = sval;
                out_matches[o] = mval;
            }
            if (slot2 >= 0) {
                size_t o = (size_t)img * NS + slot2;
                ((float4*)out_rois)[o] = b;
                out_samples[o] = sval;
                out_matches[o] = mval;
            }
        }
    }
}

extern "C" void kernel_launch(void* const* d_in, const int* in_sizes, int n_in,
                              void* d_out, int out_size) {
    const float4* rois   = (const float4*)d_in[0];  // [128, 2000, 4]
    const float*  scores = (const float*)d_in[1];   // [128, 2000, 1]
    const float4* gt     = (const float4*)d_in[2];  // [128, 100, 4]
    const float*  rnd    = (const float*)d_in[3];   // [128, 2100]
    float* out = (float*)d_out;

    const int smem_bytes = (int)sizeof(SmemLayout);
    static int configured = 0;
    if (!configured) {
        cudaFuncSetAttribute(rcnn_sampler_kernel,
                             cudaFuncAttributeMaxDynamicSharedMemorySize, smem_bytes);
        configured = 1;
    }
    rcnn_sampler_kernel<<<NI, NT, smem_bytes>>>(rois, scores, gt, rnd, out);
}

// round 12
// speedup vs baseline: 1.0019x; 1.0019x over previous
#include <cuda_runtime.h>
#include <cstdint>

typedef unsigned long long u64;

#define NI 128
#define NP 2000
#define MG 100
#define NA (NP + MG)          // 2100
#define NS 512
#define MAXPOS 128
#define NUMNEG 384
#define NT 1024
#define NG 512                // threads per specialized group
#define NB 2048               // buckets
#define CHUNK 4               // 128 % CHUNK == 0 -> boundary at warp 1

#define BAR_SORT(n)  asm volatile("bar.sync 1, %0;" :: "n"(n) : "memory")
#define BAR_CLS(n)   asm volatile("bar.sync 2, %0;" :: "n"(n) : "memory")

struct __align__(16) SmemLayout {
    float4 roi[NA];           // 33600 B: [0,2000) prefetched rois, [2000,2100) gt
    u64    skey[NA];          // 16800
    int    cnt[NB];           // 8192
    int    off[NB];           // 8192
    float  sc[NA];            // 8400: [0,2000) scores, [2000,2100) = 1.0
    float4 vbox[MG];          // 1600
    float  varea[MG];         // 400
    int    vidx[MG];          // 400  (compacted slot -> original gt index)
    short  amax[NA];          // 4200
    unsigned char cls[NA];    // 2100 (shift: 42=pos, 21=neg-cand, 0=ignore)
    int    wcnt[4];
    int    iwsum[16];         // sort-group warp partials
    u64    wsum[32];
    u64    totals, ebound;
    int    V;
};

__device__ __forceinline__ void cp16(void* s, const void* g) {
    uint32_t sa = (uint32_t)__cvta_generic_to_shared(s);
    asm volatile("cp.async.cg.shared.global [%0], [%1], 16;" :: "r"(sa), "l"(g));
}

__global__ __launch_bounds__(NT)
void rcnn_sampler_kernel(const float4* __restrict__ g_rois,   // [NI, NP]
                         const float*  __restrict__ g_scores, // [NI, NP]
                         const float4* __restrict__ g_gt,     // [NI, MG]
                         const float*  __restrict__ g_rand,   // [NI, NA]
                         float* __restrict__ out)
{
    extern __shared__ char smem_raw[];
    SmemLayout* sm = reinterpret_cast<SmemLayout*>(smem_raw);

    const int img = blockIdx.x;
    const int tid = threadIdx.x;
    const unsigned int lane = tid & 31, wd = tid >> 5;

    if (tid < NG) {
        // ================= CLASSIFY GROUP (warps 0-15) =================
        // prefetch rois (2000 float4) + scores (2000 f32 = 500 x 16B)
        const float4* rsrc = g_rois + (size_t)img * NP;
        for (int i = tid; i < NP; i += NG) cp16(&sm->roi[i], rsrc + i);
        if (tid < NP / 4) cp16(&sm->sc[tid * 4], g_scores + (size_t)img * NP + tid * 4);
        asm volatile("cp.async.commit_group;");

        // gt load + validity. Zero-area gt gives IoU == 0.0f exactly vs every
        // box (clip algebra), so skipping is bit-exact given best=0 / arg=0.
        float4 myb; float myar = 0.f; bool myval = false;
        if (tid < MG) {
            myb = g_gt[(size_t)img * MG + tid];
            sm->roi[NP + tid] = myb;          // unify: gt appended to roi[]
            sm->sc[NP + tid]  = 1.0f;
            myar = fmaxf(myb.z - myb.x, 0.f) * fmaxf(myb.w - myb.y, 0.f);
            myval = myar > 0.f;
        }
        unsigned bal = __ballot_sync(0xFFFFFFFFu, myval);
        if (lane == 0 && wd < 4) sm->wcnt[wd] = __popc(bal);

        asm volatile("cp.async.wait_group 0;");
        BAR_CLS(NG);                           // wcnt + gt stores + prefetch visible

        if (myval) {                           // compact valid gt (order-preserving)
            int off = __popc(bal & ((1u << lane) - 1));
            for (int w = 0; w < (int)wd; ++w) off += sm->wcnt[w];
            sm->vbox[off]  = myb;
            sm->varea[off] = myar;
            sm->vidx[off]  = tid;
        }
        if (tid == 0) sm->V = sm->wcnt[0] + sm->wcnt[1] + sm->wcnt[2] + sm->wcnt[3];
        BAR_CLS(NG);
        const int V = sm->V;

        // ---- classify: 4 boxes per thread in ONE loop (4 indep dep chains),
        // gt loads amortized over 4 boxes. Best tracked as exact (inter,union)
        // pair; cross-mult compare == exact-quotient argmax. RN division is
        // monotone, so the final max IoU (threshold test) matches the ref.
        {
            const int i0 = tid, i1 = tid + NG, i2 = tid + 2 * NG, i3 = tid + 3 * NG;
            float4 b0 = sm->roi[i0], b1 = sm->roi[i1], b2 = sm->roi[i2], b3 = sm->roi[i3];
            float aa0 = fmaxf(b0.z - b0.x, 0.f) * fmaxf(b0.w - b0.y, 0.f);
            float aa1 = fmaxf(b1.z - b1.x, 0.f) * fmaxf(b1.w - b1.y, 0.f);
            float aa2 = fmaxf(b2.z - b2.x, 0.f) * fmaxf(b2.w - b2.y, 0.f);
            float aa3 = fmaxf(b3.z - b3.x, 0.f) * fmaxf(b3.w - b3.y, 0.f);
            float bi0 = 0.f, bu0 = 1.f, bi1 = 0.f, bu1 = 1.f;
            float bi2 = 0.f, bu2 = 1.f, bi3 = 0.f, bu3 = 1.f;
            int a0 = 0, a1 = 0, a2 = 0, a3 = 0;
            for (int m = 0; m < V; ++m) {
                float4 g  = sm->vbox[m];
                float  ar = sm->varea[m];
                float w, h, in, un;
                w = fminf(b0.z, g.z) - fmaxf(b0.x, g.x);
                h = fminf(b0.w, g.w) - fmaxf(b0.y, g.y);
                in = fmaxf(w, 0.f) * fmaxf(h, 0.f);        // == ref clip product
                un = (aa0 + ar) - in;                      // == ref union
                if (in * bu0 > bi0 * un) { bi0 = in; bu0 = un; a0 = m; }
                w = fminf(b1.z, g.z) - fmaxf(b1.x, g.x);
                h = fminf(b1.w, g.w) - fmaxf(b1.y, g.y);
                in = fmaxf(w, 0.f) * fmaxf(h, 0.f);
                un = (aa1 + ar) - in;
                if (in * bu1 > bi1 * un) { bi1 = in; bu1 = un; a1 = m; }
                w = fminf(b2.z, g.z) - fmaxf(b2.x, g.x);
                h = fminf(b2.w, g.w) - fmaxf(b2.y, g.y);
                in = fmaxf(w, 0.f) * fmaxf(h, 0.f);
                un = (aa2 + ar) - in;
                if (in * bu2 > bi2 * un) { bi2 = in; bu2 = un; a2 = m; }
                w = fminf(b3.z, g.z) - fmaxf(b3.x, g.x);
                h = fminf(b3.w, g.w) - fmaxf(b3.y, g.y);
                in = fmaxf(w, 0.f) * fmaxf(h, 0.f);
                un = (aa3 + ar) - in;
                if (in * bu3 > bi3 * un) { bi3 = in; bu3 = un; a3 = m; }
            }
            float q0 = __fdiv_rn(bi0, bu0);   // IEEE div once per box: bit-match JAX max
            float q1 = __fdiv_rn(bi1, bu1);
            float q2 = __fdiv_rn(bi2, bu2);
            float q3 = __fdiv_rn(bi3, bu3);
            sm->cls[i0] = (q0 >= 0.5f) ? 42 : ((sm->sc[i0] < 0.f) ? 0 : 21);
            sm->cls[i1] = (q1 >= 0.5f) ? 42 : ((sm->sc[i1] < 0.f) ? 0 : 21);
            sm->cls[i2] = (q2 >= 0.5f) ? 42 : ((sm->sc[i2] < 0.f) ? 0 : 21);
            sm->cls[i3] = (q3 >= 0.5f) ? 42 : ((sm->sc[i3] < 0.f) ? 0 : 21);
            sm->amax[i0] = (short)sm->vidx[a0];   // remap compacted -> original
            sm->amax[i1] = (short)sm->vidx[a1];
            sm->amax[i2] = (short)sm->vidx[a2];
            sm->amax[i3] = (short)sm->vidx[a3];
        }
        if (tid < NA - 4 * NG) {               // boxes 2048..2099 (all gt, score=1)
            const int i4 = tid + 4 * NG;
            float4 b = sm->roi[i4];
            float aa = fmaxf(b.z - b.x, 0.f) * fmaxf(b.w - b.y, 0.f);
            float bi = 0.f, bu = 1.f; int a = 0;
            for (int m = 0; m < V; ++m) {
                float4 g  = sm->vbox[m];
                float  ar = sm->varea[m];
                float w = fminf(b.z, g.z) - fmaxf(b.x, g.x);
                float h = fminf(b.w, g.w) - fmaxf(b.y, g.y);
                float in = fmaxf(w, 0.f) * fmaxf(h, 0.f);
                float un = (aa + ar) - in;
                if (in * bu > bi * un) { bi = in; bu = un; a = m; }
            }
            float q = __fdiv_rn(bi, bu);
            sm->cls[i4]  = (q >= 0.5f) ? 42 : 21;
            sm->amax[i4] = (short)sm->vidx[a];
        }
    } else {
        // ================= SORT GROUP (warps 16-31) =================
        const int st = tid - NG;

        // zero histogram (int4 stores)
        ((int4*)sm->cnt)[st] = make_int4(0, 0, 0, 0);

        // keys: (rand_bits << 32) | idx. rand in [0,1): positive float bit
        // pattern is order-preserving; embedded idx makes ties stable, so
        // sorting these u64s == jnp.argsort(rand) exactly.
        u64 myk[5]; int mybkt[5]; int nown = 0;
        const float* rp = g_rand + (size_t)img * NA;
        #pragma unroll
        for (int e = 0; e < 5; ++e) {
            int i = st + e * NG;
            if (i < NA) {
                float r = rp[i];
                myk[e] = ((u64)__float_as_uint(r) << 32) | (unsigned int)i;
                // uniform value -> order-preserving bucket (monotone fp ops)
                mybkt[e] = min((int)(r * (float)NB), NB - 1);
                ++nown;
            }
        }
        BAR_SORT(NG);                          // zeroed cnt visible

        #pragma unroll
        for (int e = 0; e < 5; ++e)
            if (e < nown) atomicAdd(&sm->cnt[mybkt[e]], 1);
        BAR_SORT(NG);

        // exclusive scan of 2048 bins: 4 consecutive bins per thread
        {
            int c0 = sm->cnt[4 * st], c1 = sm->cnt[4 * st + 1];
            int c2 = sm->cnt[4 * st + 2], c3 = sm->cnt[4 * st + 3];
            int s4 = c0 + c1 + c2 + c3;
            int vv = s4;
            #pragma unroll
            for (int o = 1; o < 32; o <<= 1) {
                int n = __shfl_up_sync(0xFFFFFFFFu, vv, o);
                if (lane >= (unsigned)o) vv += n;
            }
            const int swd = st >> 5;           // sort-group warp 0..15
            if (lane == 31) sm->iwsum[swd] = vv;
            BAR_SORT(NG);
            if (st < 32) {                     // first sort warp scans 16 partials
                int t0 = (st < 16) ? sm->iwsum[st] : 0;
                int tv = t0;
                #pragma unroll
                for (int o = 1; o < 16; o <<= 1) {
                    int n = __shfl_up_sync(0xFFFFFFFFu, tv, o);
                    if (lane >= (unsigned)o) tv += n;
                }
                if (st < 16) sm->iwsum[st] = tv - t0;   // exclusive
            }
            BAR_SORT(NG);
            int ex = sm->iwsum[swd] + (vv - s4);
            sm->off[4 * st]     = ex;
            sm->off[4 * st + 1] = ex + c0;
            sm->off[4 * st + 2] = ex + c0 + c1;
            sm->off[4 * st + 3] = ex + c0 + c1 + c2;
        }
        BAR_SORT(NG);

        // scatter keys into bucket slots (off[b] becomes bucket END)
        #pragma unroll
        for (int e = 0; e < 5; ++e)
            if (e < nown) {
                int p = atomicAdd(&sm->off[mybkt[e]], 1);
                sm->skey[p] = myk[e];
            }
        BAR_SORT(NG);

        // per-bucket insertion sort (avg load ~1)
        for (int bb = st; bb < NB; bb += NG) {
            int end = sm->off[bb];
            int stt = end - sm->cnt[bb];
            for (int a = stt + 1; a < end; ++a) {
                u64 key = sm->skey[a];
                int p = a - 1;
                while (p >= stt && sm->skey[p] > key) { sm->skey[p + 1] = sm->skey[p]; --p; }
                sm->skey[p + 1] = key;
            }
        }
    }

    __syncthreads();   // join: skey (sort) + cls/amax/roi (classify) all visible

    // ======== phase F: packed per-class stable-rank scan ========
    // CHUNK=4: thread t covers j in [4t, 4t+4); MAXPOS=128 boundary = warp 1
    const int j0 = tid * CHUNK;
    unsigned int idxr[CHUNK]; int shr[CHUNK];
    int nj = 0;
    u64 loc = 0;
    #pragma unroll
    for (int e = 0; e < CHUNK; ++e) {
        int j = j0 + e;
        if (j < NA) {
            unsigned int idx = (unsigned int)sm->skey[j];
            int sh = sm->cls[idx];
            idxr[e] = idx; shr[e] = sh;
            loc += 1ull << sh;
            ++nj;
        }
    }
    u64 v = loc;
    #pragma unroll
    for (int o = 1; o < 32; o <<= 1) {
        u64 n = __shfl_up_sync(0xFFFFFFFFu, v, o);
        if (lane >= (unsigned)o) v += n;
    }
    if (lane == 31) sm->wsum[wd] = v;
    __syncthreads();
    if (tid < 32) {
        u64 t0 = sm->wsum[tid];
        u64 tv = t0;
        #pragma unroll
        for (int o = 1; o < 32; o <<= 1) {
            u64 n = __shfl_up_sync(0xFFFFFFFFu, tv, o);
            if (lane >= (unsigned)o) tv += n;
        }
        sm->wsum[tid] = tv - t0;                 // exclusive
        if (tid == 1)  sm->ebound = tv - t0;     // prefix over j in [0,128)
        if (tid == 31) sm->totals = tv;          // inclusive total
    }
    __syncthreads();
    const u64 excl = sm->wsum[wd] + (v - loc);

    // ======== phase G: closed-form slot assignment + output ========
    const u64 M21 = (1ull << 21) - 1;
    const u64 tot = sm->totals, ev = sm->ebound;
    const int c3  = (int)((tot >> 42) & M21);
    const int c2t = (int)((tot >> 21) & M21);
    const int e3  = (int)((ev  >> 42) & M21);
    const int e2  = (int)((ev  >> 21) & M21);
    const int e0  = (int)( ev         & M21);
    const int d2 = c2t - e2, d3 = c3 - e3;

    int r3 = (int)((excl >> 42) & M21);
    int r2 = (int)((excl >> 21) & M21);
    int r0 = (int)( excl         & M21);

    float* out_rois    = out;
    float* out_samples = out + (size_t)NI * NS * 4;
    float* out_matches = out_samples + (size_t)NI * NS;

    #pragma unroll
    for (int e = 0; e < CHUNK; ++e) {
        if (e >= nj) break;
        const int j = j0 + e;
        unsigned int idx = idxr[e];
        int sh = shr[e];
        int r;
        if (sh == 42)      r = r3++;
        else if (sh == 21) r = r2++;
        else               r = r0++;

        // top partition: priority 3 > 2 > 0, stable in j, first MAXPOS
        int tb = (sh == 42) ? 0 : (sh == 21 ? c3 : (c3 + c2t));
        int pos = tb + r;
        int slot1 = (pos < MAXPOS) ? pos : -1;

        // bottom partition: among j>=MAXPOS, priority 2 > 3 > 0, first NUMNEG
        int slot2 = -1;
        if (j >= MAXPOS) {
            int ec = (sh == 42) ? e3 : (sh == 21 ? e2 : e0);
            int bb = (sh == 21) ? 0 : (sh == 42 ? d2 : (d2 + d3));
            int pos2 = bb + (r - ec);
            if (pos2 < NUMNEG) slot2 = MAXPOS + pos2;
        }

        if (slot1 >= 0 || slot2 >= 0) {
            float4 b = sm->roi[idx];
            float sval = (sh == 42) ? 1.f : (sh == 21 ? -1.f : 0.f);
            float mval = (float)sm->amax[idx];
            if (slot1 >= 0) {
                size_t o = (size_t)img * NS + slot1;
                ((float4*)out_rois)[o] = b;
                out_samples[o] = sval;
                out_matches[o] = mval;
            }
            if (slot2 >= 0) {
                size_t o = (size_t)img * NS + slot2;
                ((float4*)out_rois)[o] = b;
                out_samples[o] = sval;
                out_matches[o] = mval;
            }
        }
    }
}

extern "C" void kernel_launch(void* const* d_in, const int* in_sizes, int n_in,
                              void* d_out, int out_size) {
    const float4* rois   = (const float4*)d_in[0];  // [128, 2000, 4]
    const float*  scores = (const float*)d_in[1];   // [128, 2000, 1]
    const float4* gt     = (const float4*)d_in[2];  // [128, 100, 4]
    const float*  rnd    = (const float*)d_in[3];   // [128, 2100]
    float* out = (float*)d_out;

    const int smem_bytes = (int)sizeof(SmemLayout);
    static int configured = 0;
    if (!configured) {
        cudaFuncSetAttribute(rcnn_sampler_kernel,
                             cudaFuncAttributeMaxDynamicSharedMemorySize, smem_bytes);
        configured = 1;
    }
    rcnn_sampler_kernel<<<NI, NT, smem_bytes>>>(rois, scores, gt, rnd, out);
}

// round 13
// speedup vs baseline: 1.0152x; 1.0133x over previous
#include <cuda_runtime.h>
#include <cstdint>

typedef unsigned long long u64;

#define NI 128
#define NP 2000
#define MG 100
#define NA (NP + MG)          // 2100
#define NS 512
#define MAXPOS 128
#define NUMNEG 384
#define NT 1024
#define NG 512                // threads per specialized group
#define NB 2048               // buckets
#define CHUNK 4               // 128 % CHUNK == 0 -> boundary at warp 1

#define BAR_SORT(n)  asm volatile("bar.sync 1, %0;" :: "n"(n) : "memory")
#define BAR_CLS(n)   asm volatile("bar.sync 2, %0;" :: "n"(n) : "memory")

struct __align__(16) SmemLayout {
    float4 roi[NA];           // 33600 B: [0,2000) prefetched rois, [2000,2100) gt
    u64    skey[NA];          // 16800 (final sorted keys)
    u64    tmp[NA];           // 16800 (arrival-order scatter)
    int    cnt[NB];           // 8192
    int    off[NB];           // 8192
    float  sc[NA];            // 8400: [0,2000) scores, [2000,2100) = 1.0
    float4 vbox[MG];          // 1600
    float  varea[MG];         // 400
    int    vidx[MG];          // 400  (compacted slot -> original gt index)
    short  amax[NA];          // 4200
    unsigned char cls[NA];    // 2100 (shift: 42=pos, 21=neg-cand, 0=ignore)
    int    wcnt[4];
    int    iwsum[16];         // sort-group warp partials
    u64    wsum[32];
    u64    totals, ebound;
    int    V;
};

__device__ __forceinline__ void cp16(void* s, const void* g) {
    uint32_t sa = (uint32_t)__cvta_generic_to_shared(s);
    asm volatile("cp.async.cg.shared.global [%0], [%1], 16;" :: "r"(sa), "l"(g));
}

__global__ __launch_bounds__(NT)
void rcnn_sampler_kernel(const float4* __restrict__ g_rois,   // [NI, NP]
                         const float*  __restrict__ g_scores, // [NI, NP]
                         const float4* __restrict__ g_gt,     // [NI, MG]
                         const float*  __restrict__ g_rand,   // [NI, NA]
                         float* __restrict__ out)
{
    extern __shared__ char smem_raw[];
    SmemLayout* sm = reinterpret_cast<SmemLayout*>(smem_raw);

    const int img = blockIdx.x;
    const int tid = threadIdx.x;
    const unsigned int lane = tid & 31, wd = tid >> 5;

    if (tid < NG) {
        // ================= CLASSIFY GROUP (warps 0-15) =================
        // prefetch rois (2000 float4) + scores (2000 f32 = 500 x 16B)
        const float4* rsrc = g_rois + (size_t)img * NP;
        for (int i = tid; i < NP; i += NG) cp16(&sm->roi[i], rsrc + i);
        if (tid < NP / 4) cp16(&sm->sc[tid * 4], g_scores + (size_t)img * NP + tid * 4);
        asm volatile("cp.async.commit_group;");

        // gt load + validity. Zero-area gt gives IoU == 0.0f exactly vs every
        // box (clip algebra), so skipping is bit-exact given best=0 / arg=0.
        float4 myb; float myar = 0.f; bool myval = false;
        if (tid < MG) {
            myb = g_gt[(size_t)img * MG + tid];
            sm->roi[NP + tid] = myb;          // unify: gt appended to roi[]
            sm->sc[NP + tid]  = 1.0f;
            myar = fmaxf(myb.z - myb.x, 0.f) * fmaxf(myb.w - myb.y, 0.f);
            myval = myar > 0.f;
        }
        unsigned bal = __ballot_sync(0xFFFFFFFFu, myval);
        if (lane == 0 && wd < 4) sm->wcnt[wd] = __popc(bal);

        asm volatile("cp.async.wait_group 0;");
        BAR_CLS(NG);                           // wcnt + gt stores + prefetch visible

        if (myval) {                           // compact valid gt (order-preserving)
            int off = __popc(bal & ((1u << lane) - 1));
            for (int w = 0; w < (int)wd; ++w) off += sm->wcnt[w];
            sm->vbox[off]  = myb;
            sm->varea[off] = myar;
            sm->vidx[off]  = tid;
        }
        if (tid == 0) sm->V = sm->wcnt[0] + sm->wcnt[1] + sm->wcnt[2] + sm->wcnt[3];
        BAR_CLS(NG);
        const int V = sm->V;

        // ---- classify: 4 boxes per thread in ONE loop (4 indep dep chains).
        // Best tracked as exact (inter, union) pair; cross-mult compare ==
        // exact-quotient argmax. RN division is monotone, so the final max
        // IoU (threshold test) matches the reference bit-for-bit.
        {
            const int i0 = tid, i1 = tid + NG, i2 = tid + 2 * NG, i3 = tid + 3 * NG;
            float4 b0 = sm->roi[i0], b1 = sm->roi[i1], b2 = sm->roi[i2], b3 = sm->roi[i3];
            float aa0 = fmaxf(b0.z - b0.x, 0.f) * fmaxf(b0.w - b0.y, 0.f);
            float aa1 = fmaxf(b1.z - b1.x, 0.f) * fmaxf(b1.w - b1.y, 0.f);
            float aa2 = fmaxf(b2.z - b2.x, 0.f) * fmaxf(b2.w - b2.y, 0.f);
            float aa3 = fmaxf(b3.z - b3.x, 0.f) * fmaxf(b3.w - b3.y, 0.f);
            float bi0 = 0.f, bu0 = 1.f, bi1 = 0.f, bu1 = 1.f;
            float bi2 = 0.f, bu2 = 1.f, bi3 = 0.f, bu3 = 1.f;
            int a0 = 0, a1 = 0, a2 = 0, a3 = 0;
            for (int m = 0; m < V; ++m) {
                float4 g  = sm->vbox[m];
                float  ar = sm->varea[m];
                float w, h, in, un;
                w = fminf(b0.z, g.z) - fmaxf(b0.x, g.x);
                h = fminf(b0.w, g.w) - fmaxf(b0.y, g.y);
                in = fmaxf(w, 0.f) * fmaxf(h, 0.f);        // == ref clip product
                un = (aa0 + ar) - in;                      // == ref union
                if (in * bu0 > bi0 * un) { bi0 = in; bu0 = un; a0 = m; }
                w = fminf(b1.z, g.z) - fmaxf(b1.x, g.x);
                h = fminf(b1.w, g.w) - fmaxf(b1.y, g.y);
                in = fmaxf(w, 0.f) * fmaxf(h, 0.f);
                un = (aa1 + ar) - in;
                if (in * bu1 > bi1 * un) { bi1 = in; bu1 = un; a1 = m; }
                w = fminf(b2.z, g.z) - fmaxf(b2.x, g.x);
                h = fminf(b2.w, g.w) - fmaxf(b2.y, g.y);
                in = fmaxf(w, 0.f) * fmaxf(h, 0.f);
                un = (aa2 + ar) - in;
                if (in * bu2 > bi2 * un) { bi2 = in; bu2 = un; a2 = m; }
                w = fminf(b3.z, g.z) - fmaxf(b3.x, g.x);
                h = fminf(b3.w, g.w) - fmaxf(b3.y, g.y);
                in = fmaxf(w, 0.f) * fmaxf(h, 0.f);
                un = (aa3 + ar) - in;
                if (in * bu3 > bi3 * un) { bi3 = in; bu3 = un; a3 = m; }
            }
            float q0 = __fdiv_rn(bi0, bu0);   // IEEE div once per box: bit-match JAX max
            float q1 = __fdiv_rn(bi1, bu1);
            float q2 = __fdiv_rn(bi2, bu2);
            float q3 = __fdiv_rn(bi3, bu3);
            sm->cls[i0] = (q0 >= 0.5f) ? 42 : ((sm->sc[i0] < 0.f) ? 0 : 21);
            sm->cls[i1] = (q1 >= 0.5f) ? 42 : ((sm->sc[i1] < 0.f) ? 0 : 21);
            sm->cls[i2] = (q2 >= 0.5f) ? 42 : ((sm->sc[i2] < 0.f) ? 0 : 21);
            sm->cls[i3] = (q3 >= 0.5f) ? 42 : ((sm->sc[i3] < 0.f) ? 0 : 21);
            sm->amax[i0] = (short)sm->vidx[a0];   // remap compacted -> original
            sm->amax[i1] = (short)sm->vidx[a1];
            sm->amax[i2] = (short)sm->vidx[a2];
            sm->amax[i3] = (short)sm->vidx[a3];
        }
        if (tid < NA - 4 * NG) {               // boxes 2048..2099 (all gt, score=1)
            const int i4 = tid + 4 * NG;
            float4 b = sm->roi[i4];
            float aa = fmaxf(b.z - b.x, 0.f) * fmaxf(b.w - b.y, 0.f);
            float bi = 0.f, bu = 1.f; int a = 0;
            for (int m = 0; m < V; ++m) {
                float4 g  = sm->vbox[m];
                float  ar = sm->varea[m];
                float w = fminf(b.z, g.z) - fmaxf(b.x, g.x);
                float h = fminf(b.w, g.w) - fmaxf(b.y, g.y);
                float in = fmaxf(w, 0.f) * fmaxf(h, 0.f);
                float un = (aa + ar) - in;
                if (in * bu > bi * un) { bi = in; bu = un; a = m; }
            }
            float q = __fdiv_rn(bi, bu);
            sm->cls[i4]  = (q >= 0.5f) ? 42 : 21;
            sm->amax[i4] = (short)sm->vidx[a];
        }
    } else {
        // ================= SORT GROUP (warps 16-31) =================
        const int st = tid - NG;

        // zero histogram (int4 stores)
        ((int4*)sm->cnt)[st] = make_int4(0, 0, 0, 0);

        // keys: (rand_bits << 32) | idx. rand in [0,1): positive float bit
        // pattern is order-preserving; embedded idx makes ties stable AND
        // keys globally unique, so sorting == jnp.argsort(rand) exactly.
        u64 myk[5]; int mybkt[5]; int nown = 0;
        const float* rp = g_rand + (size_t)img * NA;
        #pragma unroll
        for (int e = 0; e < 5; ++e) {
            int i = st + e * NG;
            if (i < NA) {
                float r = rp[i];
                myk[e] = ((u64)__float_as_uint(r) << 32) | (unsigned int)i;
                // uniform value -> order-preserving bucket (monotone fp ops)
                mybkt[e] = min((int)(r * (float)NB), NB - 1);
                ++nown;
            }
        }
        BAR_SORT(NG);                          // zeroed cnt visible

        #pragma unroll
        for (int e = 0; e < 5; ++e)
            if (e < nown) atomicAdd(&sm->cnt[mybkt[e]], 1);
        BAR_SORT(NG);

        // exclusive scan of 2048 bins: 4 consecutive bins per thread
        {
            int c0 = sm->cnt[4 * st], c1 = sm->cnt[4 * st + 1];
            int c2 = sm->cnt[4 * st + 2], c3 = sm->cnt[4 * st + 3];
            int s4 = c0 + c1 + c2 + c3;
            int vv = s4;
            #pragma unroll
            for (int o = 1; o < 32; o <<= 1) {
                int n = __shfl_up_sync(0xFFFFFFFFu, vv, o);
                if (lane >= (unsigned)o) vv += n;
            }
            const int swd = st >> 5;           // sort-group warp 0..15
            if (lane == 31) sm->iwsum[swd] = vv;
            BAR_SORT(NG);
            if (st < 32) {                     // first sort warp scans 16 partials
                int t0 = (st < 16) ? sm->iwsum[st] : 0;
                int tv = t0;
                #pragma unroll
                for (int o = 1; o < 16; o <<= 1) {
                    int n = __shfl_up_sync(0xFFFFFFFFu, tv, o);
                    if (lane >= (unsigned)o) tv += n;
                }
                if (st < 16) sm->iwsum[st] = tv - t0;   // exclusive
            }
            BAR_SORT(NG);
            int ex = sm->iwsum[swd] + (vv - s4);
            sm->off[4 * st]     = ex;
            sm->off[4 * st + 1] = ex + c0;
            sm->off[4 * st + 2] = ex + c0 + c1;
            sm->off[4 * st + 3] = ex + c0 + c1 + c2;
        }
        BAR_SORT(NG);

        // scatter keys into bucket slots in arrival order (off[b] -> END)
        #pragma unroll
        for (int e = 0; e < 5; ++e)
            if (e < nown) {
                int p = atomicAdd(&sm->off[mybkt[e]], 1);
                sm->tmp[p] = myk[e];
            }
        BAR_SORT(NG);

        // element-parallel rank-scatter: each element counts its bucket
        // peers with smaller key (keys unique -> exact rank), then writes
        // itself to its final sorted slot. Avg bucket ~1-2, max ~8; all
        // loads independent (no serial insertion chain).
        #pragma unroll
        for (int e = 0; e < 5; ++e)
            if (e < nown) {
                int b   = mybkt[e];
                int end = sm->off[b];
                int beg = end - sm->cnt[b];
                u64 key = myk[e];
                int rank = 0;
                for (int q = beg; q < end; ++q)
                    rank += (sm->tmp[q] < key);
                sm->skey[beg + rank] = key;
            }
    }

    __syncthreads();   // join: skey (sort) + cls/amax/roi (classify) all visible

    // ======== phase F: packed per-class stable-rank scan ========
    // CHUNK=4: thread t covers j in [4t, 4t+4); MAXPOS=128 boundary = warp 1
    const int j0 = tid * CHUNK;
    unsigned int idxr[CHUNK]; int shr[CHUNK];
    int nj = 0;
    u64 loc = 0;
    #pragma unroll
    for (int e = 0; e < CHUNK; ++e) {
        int j = j0 + e;
        if (j < NA) {
            unsigned int idx = (unsigned int)sm->skey[j];
            int sh = sm->cls[idx];
            idxr[e] = idx; shr[e] = sh;
            loc += 1ull << sh;
            ++nj;
        }
    }
    u64 v = loc;
    #pragma unroll
    for (int o = 1; o < 32; o <<= 1) {
        u64 n = __shfl_up_sync(0xFFFFFFFFu, v, o);
        if (lane >= (unsigned)o) v += n;
    }
    if (lane == 31) sm->wsum[wd] = v;
    __syncthreads();
    if (tid < 32) {
        u64 t0 = sm->wsum[tid];
        u64 tv = t0;
        #pragma unroll
        for (int o = 1; o < 32; o <<= 1) {
            u64 n = __shfl_up_sync(0xFFFFFFFFu, tv, o);
            if (lane >= (unsigned)o) tv += n;
        }
        sm->wsum[tid] = tv - t0;                 // exclusive
        if (tid == 1)  sm->ebound = tv - t0;     // prefix over j in [0,128)
        if (tid == 31) sm->totals = tv;          // inclusive total
    }
    __syncthreads();
    const u64 excl = sm->wsum[wd] + (v - loc);

    // ======== phase G: closed-form slot assignment + output ========
    const u64 M21 = (1ull << 21) - 1;
    const u64 tot = sm->totals, ev = sm->ebound;
    const int c3  = (int)((tot >> 42) & M21);
    const int c2t = (int)((tot >> 21) & M21);
    const int e3  = (int)((ev  >> 42) & M21);
    const int e2  = (int)((ev  >> 21) & M21);
    const int e0  = (int)( ev         & M21);
    const int d2 = c2t - e2, d3 = c3 - e3;

    int r3 = (int)((excl >> 42) & M21);
    int r2 = (int)((excl >> 21) & M21);
    int r0 = (int)( excl         & M21);

    float* out_rois    = out;
    float* out_samples = out + (size_t)NI * NS * 4;
    float* out_matches = out_samples + (size_t)NI * NS;

    #pragma unroll
    for (int e = 0; e < CHUNK; ++e) {
        if (e >= nj) break;
        const int j = j0 + e;
        unsigned int idx = idxr[e];
        int sh = shr[e];
        int r;
        if (sh == 42)      r = r3++;
        else if (sh == 21) r = r2++;
        else               r = r0++;

        // top partition: priority 3 > 2 > 0, stable in j, first MAXPOS
        int tb = (sh == 42) ? 0 : (sh == 21 ? c3 : (c3 + c2t));
        int pos = tb + r;
        int slot1 = (pos < MAXPOS) ? pos : -1;

        // bottom partition: among j>=MAXPOS, priority 2 > 3 > 0, first NUMNEG
        int slot2 = -1;
        if (j >= MAXPOS) {
            int ec = (sh == 42) ? e3 : (sh == 21 ? e2 : e0);
            int bb = (sh == 21) ? 0 : (sh == 42 ? d2 : (d2 + d3));
            int pos2 = bb + (r - ec);
            if (pos2 < NUMNEG) slot2 = MAXPOS + pos2;
        }

        if (slot1 >= 0 || slot2 >= 0) {
            float4 b = sm->roi[idx];
            float sval = (sh == 42) ? 1.f : (sh == 21 ? -1.f : 0.f);
            float mval = (float)sm->amax[idx];
            if (slot1 >= 0) {
                size_t o = (size_t)img * NS + slot1;
                ((float4*)out_rois)[o] = b;
                out_samples[o] = sval;
                out_matches[o] = mval;
            }
            if (slot2 >= 0) {
                size_t o = (size_t)img * NS + slot2;
                ((float4*)out_rois)[o] = b;
                out_samples[o] = sval;
                out_matches[o] = mval;
            }
        }
    }
}

extern "C" void kernel_launch(void* const* d_in, const int* in_sizes, int n_in,
                              void* d_out, int out_size) {
    const float4* rois   = (const float4*)d_in[0];  // [128, 2000, 4]
    const float*  scores = (const float*)d_in[1];   // [128, 2000, 1]
    const float4* gt     = (const float4*)d_in[2];  // [128, 100, 4]
    const float*  rnd    = (const float*)d_in[3];   // [128, 2100]
    float* out = (float*)d_out;

    const int smem_bytes = (int)sizeof(SmemLayout);
    static int configured = 0;
    if (!configured) {
        cudaFuncSetAttribute(rcnn_sampler_kernel,
                             cudaFuncAttributeMaxDynamicSharedMemorySize, smem_bytes);
        configured = 1;
    }
    rcnn_sampler_kernel<<<NI, NT, smem_bytes>>>(rois, scores, gt, rnd, out);
}

// round 14
// speedup vs baseline: 1.0171x; 1.0019x over previous
#include <cuda_runtime.h>
#include <cstdint>

typedef unsigned long long u64;

#define NI 128
#define GRID_PAD 160          // >=148 disables pSmIssueThrottle (B300 uarch note)
#define NP 2000
#define MG 100
#define NA (NP + MG)          // 2100
#define NS 512
#define MAXPOS 128
#define NUMNEG 384
#define NT 1024
#define NG 512                // threads per specialized group
#define NB 2048               // buckets
#define CHUNK 4               // 128 % CHUNK == 0 -> boundary at warp 1

#define BAR_SORT(n)  asm volatile("bar.sync 1, %0;" :: "n"(n) : "memory")
#define BAR_CLS(n)   asm volatile("bar.sync 2, %0;" :: "n"(n) : "memory")

struct __align__(16) SmemLayout {
    float4 roi[NA];           // 33600 B: [0,2000) prefetched rois, [2000,2100) gt
    u64    skey[NA];          // 16800 (final sorted keys)
    u64    tmp[NA];           // 16800 (arrival-order scatter)
    int    cnt[NB];           // 8192
    int    off[NB];           // 8192
    float  sc[NA];            // 8400: [0,2000) scores, [2000,2100) = 1.0
    float4 vbox[MG];          // 1600
    float  varea[MG];         // 400
    int    vidx[MG];          // 400  (compacted slot -> original gt index)
    short  amax[NA];          // 4200
    unsigned char cls[NA];    // 2100 (shift: 42=pos, 21=neg-cand, 0=ignore)
    int    wcnt[4];
    int    iwsum[16];         // sort-group warp partials
    u64    wsum[32];
    u64    totals, ebound;
    int    V;
};

__device__ __forceinline__ void cp16(void* s, const void* g) {
    uint32_t sa = (uint32_t)__cvta_generic_to_shared(s);
    asm volatile("cp.async.cg.shared.global [%0], [%1], 16;" :: "r"(sa), "l"(g));
}

__global__ __launch_bounds__(NT)
void rcnn_sampler_kernel(const float4* __restrict__ g_rois,   // [NI, NP]
                         const float*  __restrict__ g_scores, // [NI, NP]
                         const float4* __restrict__ g_gt,     // [NI, MG]
                         const float*  __restrict__ g_rand,   // [NI, NA]
                         float* __restrict__ out)
{
    // padding CTAs (>= NI) exist only to push grid >= 148; exit immediately
    if (blockIdx.x >= NI) return;

    extern __shared__ char smem_raw[];
    SmemLayout* sm = reinterpret_cast<SmemLayout*>(smem_raw);

    const int img = blockIdx.x;
    const int tid = threadIdx.x;
    const unsigned int lane = tid & 31, wd = tid >> 5;

    if (tid < NG) {
        // ================= CLASSIFY GROUP (warps 0-15) =================
        // prefetch rois (2000 float4) + scores (2000 f32 = 500 x 16B)
        const float4* rsrc = g_rois + (size_t)img * NP;
        for (int i = tid; i < NP; i += NG) cp16(&sm->roi[i], rsrc + i);
        if (tid < NP / 4) cp16(&sm->sc[tid * 4], g_scores + (size_t)img * NP + tid * 4);
        asm volatile("cp.async.commit_group;");

        // gt load + validity. Zero-area gt gives IoU == 0.0f exactly vs every
        // box (clip algebra), so skipping is bit-exact given best=0 / arg=0.
        float4 myb; float myar = 0.f; bool myval = false;
        if (tid < MG) {
            myb = g_gt[(size_t)img * MG + tid];
            sm->roi[NP + tid] = myb;          // unify: gt appended to roi[]
            sm->sc[NP + tid]  = 1.0f;
            myar = fmaxf(myb.z - myb.x, 0.f) * fmaxf(myb.w - myb.y, 0.f);
            myval = myar > 0.f;
        }
        unsigned bal = __ballot_sync(0xFFFFFFFFu, myval);
        if (lane == 0 && wd < 4) sm->wcnt[wd] = __popc(bal);

        asm volatile("cp.async.wait_group 0;");
        BAR_CLS(NG);                           // wcnt + gt stores + prefetch visible

        if (myval) {                           // compact valid gt (order-preserving)
            int off = __popc(bal & ((1u << lane) - 1));
            for (int w = 0; w < (int)wd; ++w) off += sm->wcnt[w];
            sm->vbox[off]  = myb;
            sm->varea[off] = myar;
            sm->vidx[off]  = tid;
        }
        if (tid == 0) sm->V = sm->wcnt[0] + sm->wcnt[1] + sm->wcnt[2] + sm->wcnt[3];
        BAR_CLS(NG);
        const int V = sm->V;

        // ---- classify: 4 boxes per thread in ONE loop (4 indep dep chains).
        // Best tracked as exact (inter, union) pair; cross-mult compare ==
        // exact-quotient argmax. RN division is monotone, so the final max
        // IoU (threshold test) matches the reference bit-for-bit.
        {
            const int i0 = tid, i1 = tid + NG, i2 = tid + 2 * NG, i3 = tid + 3 * NG;
            float4 b0 = sm->roi[i0], b1 = sm->roi[i1], b2 = sm->roi[i2], b3 = sm->roi[i3];
            float aa0 = fmaxf(b0.z - b0.x, 0.f) * fmaxf(b0.w - b0.y, 0.f);
            float aa1 = fmaxf(b1.z - b1.x, 0.f) * fmaxf(b1.w - b1.y, 0.f);
            float aa2 = fmaxf(b2.z - b2.x, 0.f) * fmaxf(b2.w - b2.y, 0.f);
            float aa3 = fmaxf(b3.z - b3.x, 0.f) * fmaxf(b3.w - b3.y, 0.f);
            float bi0 = 0.f, bu0 = 1.f, bi1 = 0.f, bu1 = 1.f;
            float bi2 = 0.f, bu2 = 1.f, bi3 = 0.f, bu3 = 1.f;
            int a0 = 0, a1 = 0, a2 = 0, a3 = 0;
            for (int m = 0; m < V; ++m) {
                float4 g  = sm->vbox[m];
                float  ar = sm->varea[m];
                float w, h, in, un;
                w = fminf(b0.z, g.z) - fmaxf(b0.x, g.x);
                h = fminf(b0.w, g.w) - fmaxf(b0.y, g.y);
                in = fmaxf(w, 0.f) * fmaxf(h, 0.f);        // == ref clip product
                un = (aa0 + ar) - in;                      // == ref union
                if (in * bu0 > bi0 * un) { bi0 = in; bu0 = un; a0 = m; }
                w = fminf(b1.z, g.z) - fmaxf(b1.x, g.x);
                h = fminf(b1.w, g.w) - fmaxf(b1.y, g.y);
                in = fmaxf(w, 0.f) * fmaxf(h, 0.f);
                un = (aa1 + ar) - in;
                if (in * bu1 > bi1 * un) { bi1 = in; bu1 = un; a1 = m; }
                w = fminf(b2.z, g.z) - fmaxf(b2.x, g.x);
                h = fminf(b2.w, g.w) - fmaxf(b2.y, g.y);
                in = fmaxf(w, 0.f) * fmaxf(h, 0.f);
                un = (aa2 + ar) - in;
                if (in * bu2 > bi2 * un) { bi2 = in; bu2 = un; a2 = m; }
                w = fminf(b3.z, g.z) - fmaxf(b3.x, g.x);
                h = fminf(b3.w, g.w) - fmaxf(b3.y, g.y);
                in = fmaxf(w, 0.f) * fmaxf(h, 0.f);
                un = (aa3 + ar) - in;
                if (in * bu3 > bi3 * un) { bi3 = in; bu3 = un; a3 = m; }
            }
            float q0 = __fdiv_rn(bi0, bu0);   // IEEE div once per box: bit-match JAX max
            float q1 = __fdiv_rn(bi1, bu1);
            float q2 = __fdiv_rn(bi2, bu2);
            float q3 = __fdiv_rn(bi3, bu3);
            sm->cls[i0] = (q0 >= 0.5f) ? 42 : ((sm->sc[i0] < 0.f) ? 0 : 21);
            sm->cls[i1] = (q1 >= 0.5f) ? 42 : ((sm->sc[i1] < 0.f) ? 0 : 21);
            sm->cls[i2] = (q2 >= 0.5f) ? 42 : ((sm->sc[i2] < 0.f) ? 0 : 21);
            sm->cls[i3] = (q3 >= 0.5f) ? 42 : ((sm->sc[i3] < 0.f) ? 0 : 21);
            sm->amax[i0] = (short)sm->vidx[a0];   // remap compacted -> original
            sm->amax[i1] = (short)sm->vidx[a1];
            sm->amax[i2] = (short)sm->vidx[a2];
            sm->amax[i3] = (short)sm->vidx[a3];
        }
        if (tid < NA - 4 * NG) {               // boxes 2048..2099 (all gt, score=1)
            const int i4 = tid + 4 * NG;
            float4 b = sm->roi[i4];
            float aa = fmaxf(b.z - b.x, 0.f) * fmaxf(b.w - b.y, 0.f);
            float bi = 0.f, bu = 1.f; int a = 0;
            for (int m = 0; m < V; ++m) {
                float4 g  = sm->vbox[m];
                float  ar = sm->varea[m];
                float w = fminf(b.z, g.z) - fmaxf(b.x, g.x);
                float h = fminf(b.w, g.w) - fmaxf(b.y, g.y);
                float in = fmaxf(w, 0.f) * fmaxf(h, 0.f);
                float un = (aa + ar) - in;
                if (in * bu > bi * un) { bi = in; bu = un; a = m; }
            }
            float q = __fdiv_rn(bi, bu);
            sm->cls[i4]  = (q >= 0.5f) ? 42 : 21;
            sm->amax[i4] = (short)sm->vidx[a];
        }
    } else {
        // ================= SORT GROUP (warps 16-31) =================
        const int st = tid - NG;

        // zero histogram (int4 stores)
        ((int4*)sm->cnt)[st] = make_int4(0, 0, 0, 0);

        // keys: (rand_bits << 32) | idx. rand in [0,1): positive float bit
        // pattern is order-preserving; embedded idx makes ties stable AND
        // keys globally unique, so sorting == jnp.argsort(rand) exactly.
        u64 myk[5]; int mybkt[5]; int nown = 0;
        const float* rp = g_rand + (size_t)img * NA;
        #pragma unroll
        for (int e = 0; e < 5; ++e) {
            int i = st + e * NG;
            if (i < NA) {
                float r = rp[i];
                myk[e] = ((u64)__float_as_uint(r) << 32) | (unsigned int)i;
                // uniform value -> order-preserving bucket (monotone fp ops)
                mybkt[e] = min((int)(r * (float)NB), NB - 1);
                ++nown;
            }
        }
        BAR_SORT(NG);                          // zeroed cnt visible

        #pragma unroll
        for (int e = 0; e < 5; ++e)
            if (e < nown) atomicAdd(&sm->cnt[mybkt[e]], 1);
        BAR_SORT(NG);

        // exclusive scan of 2048 bins: 4 consecutive bins per thread
        {
            int c0 = sm->cnt[4 * st], c1 = sm->cnt[4 * st + 1];
            int c2 = sm->cnt[4 * st + 2], c3 = sm->cnt[4 * st + 3];
            int s4 = c0 + c1 + c2 + c3;
            int vv = s4;
            #pragma unroll
            for (int o = 1; o < 32; o <<= 1) {
                int n = __shfl_up_sync(0xFFFFFFFFu, vv, o);
                if (lane >= (unsigned)o) vv += n;
            }
            const int swd = st >> 5;           // sort-group warp 0..15
            if (lane == 31) sm->iwsum[swd] = vv;
            BAR_SORT(NG);
            if (st < 32) {                     // first sort warp scans 16 partials
                int t0 = (st < 16) ? sm->iwsum[st] : 0;
                int tv = t0;
                #pragma unroll
                for (int o = 1; o < 16; o <<= 1) {
                    int n = __shfl_up_sync(0xFFFFFFFFu, tv, o);
                    if (lane >= (unsigned)o) tv += n;
                }
                if (st < 16) sm->iwsum[st] = tv - t0;   // exclusive
            }
            BAR_SORT(NG);
            int ex = sm->iwsum[swd] + (vv - s4);
            sm->off[4 * st]     = ex;
            sm->off[4 * st + 1] = ex + c0;
            sm->off[4 * st + 2] = ex + c0 + c1;
            sm->off[4 * st + 3] = ex + c0 + c1 + c2;
        }
        BAR_SORT(NG);

        // scatter keys into bucket slots in arrival order (off[b] -> END)
        #pragma unroll
        for (int e = 0; e < 5; ++e)
            if (e < nown) {
                int p = atomicAdd(&sm->off[mybkt[e]], 1);
                sm->tmp[p] = myk[e];
            }
        BAR_SORT(NG);

        // element-parallel rank-scatter: each element counts its bucket
        // peers with smaller key (keys unique -> exact rank), then writes
        // itself to its final sorted slot. Avg bucket ~1-2, max ~8; all
        // loads independent (no serial insertion chain).
        #pragma unroll
        for (int e = 0; e < 5; ++e)
            if (e < nown) {
                int b   = mybkt[e];
                int end = sm->off[b];
                int beg = end - sm->cnt[b];
                u64 key = myk[e];
                int rank = 0;
                for (int q = beg; q < end; ++q)
                    rank += (sm->tmp[q] < key);
                sm->skey[beg + rank] = key;
            }
    }

    __syncthreads();   // join: skey (sort) + cls/amax/roi (classify) all visible

    // ======== phase F: packed per-class stable-rank scan ========
    // CHUNK=4: thread t covers j in [4t, 4t+4); MAXPOS=128 boundary = warp 1
    const int j0 = tid * CHUNK;
    unsigned int idxr[CHUNK]; int shr[CHUNK];
    int nj = 0;
    u64 loc = 0;
    #pragma unroll
    for (int e = 0; e < CHUNK; ++e) {
        int j = j0 + e;
        if (j < NA) {
            unsigned int idx = (unsigned int)sm->skey[j];
            int sh = sm->cls[idx];
            idxr[e] = idx; shr[e] = sh;
            loc += 1ull << sh;
            ++nj;
        }
    }
    u64 v = loc;
    #pragma unroll
    for (int o = 1; o < 32; o <<= 1) {
        u64 n = __shfl_up_sync(0xFFFFFFFFu, v, o);
        if (lane >= (unsigned)o) v += n;
    }
    if (lane == 31) sm->wsum[wd] = v;
    __syncthreads();
    if (tid < 32) {
        u64 t0 = sm->wsum[tid];
        u64 tv = t0;
        #pragma unroll
        for (int o = 1; o < 32; o <<= 1) {
            u64 n = __shfl_up_sync(0xFFFFFFFFu, tv, o);
            if (lane >= (unsigned)o) tv += n;
        }
        sm->wsum[tid] = tv - t0;                 // exclusive
        if (tid == 1)  sm->ebound = tv - t0;     // prefix over j in [0,128)
        if (tid == 31) sm->totals = tv;          // inclusive total
    }
    __syncthreads();
    const u64 excl = sm->wsum[wd] + (v - loc);

    // ======== phase G: closed-form slot assignment + output ========
    const u64 M21 = (1ull << 21) - 1;
    const u64 tot = sm->totals, ev = sm->ebound;
    const int c3  = (int)((tot >> 42) & M21);
    const int c2t = (int)((tot >> 21) & M21);
    const int e3  = (int)((ev  >> 42) & M21);
    const int e2  = (int)((ev  >> 21) & M21);
    const int e0  = (int)( ev         & M21);
    const int d2 = c2t - e2, d3 = c3 - e3;

    int r3 = (int)((excl >> 42) & M21);
    int r2 = (int)((excl >> 21) & M21);
    int r0 = (int)( excl         & M21);

    float* out_rois    = out;
    float* out_samples = out + (size_t)NI * NS * 4;
    float* out_matches = out_samples + (size_t)NI * NS;

    #pragma unroll
    for (int e = 0; e < CHUNK; ++e) {
        if (e >= nj) break;
        const int j = j0 + e;
        unsigned int idx = idxr[e];
        int sh = shr[e];
        int r;
        if (sh == 42)      r = r3++;
        else if (sh == 21) r = r2++;
        else               r = r0++;

        // top partition: priority 3 > 2 > 0, stable in j, first MAXPOS
        int tb = (sh == 42) ? 0 : (sh == 21 ? c3 : (c3 + c2t));
        int pos = tb + r;
        int slot1 = (pos < MAXPOS) ? pos : -1;

        // bottom partition: among j>=MAXPOS, priority 2 > 3 > 0, first NUMNEG
        int slot2 = -1;
        if (j >= MAXPOS) {
            int ec = (sh == 42) ? e3 : (sh == 21 ? e2 : e0);
            int bb = (sh == 21) ? 0 : (sh == 42 ? d2 : (d2 + d3));
            int pos2 = bb + (r - ec);
            if (pos2 < NUMNEG) slot2 = MAXPOS + pos2;
        }

        if (slot1 >= 0 || slot2 >= 0) {
            float4 b = sm->roi[idx];
            float sval = (sh == 42) ? 1.f : (sh == 21 ? -1.f : 0.f);
            float mval = (float)sm->amax[idx];
            if (slot1 >= 0) {
                size_t o = (size_t)img * NS + slot1;
                ((float4*)out_rois)[o] = b;
                out_samples[o] = sval;
                out_matches[o] = mval;
            }
            if (slot2 >= 0) {
                size_t o = (size_t)img * NS + slot2;
                ((float4*)out_rois)[o] = b;
                out_samples[o] = sval;
                out_matches[o] = mval;
            }
        }
    }
}

extern "C" void kernel_launch(void* const* d_in, const int* in_sizes, int n_in,
                              void* d_out, int out_size) {
    const float4* rois   = (const float4*)d_in[0];  // [128, 2000, 4]
    const float*  scores = (const float*)d_in[1];   // [128, 2000, 1]
    const float4* gt     = (const float4*)d_in[2];  // [128, 100, 4]
    const float*  rnd    = (const float*)d_in[3];   // [128, 2100]
    float* out = (float*)d_out;

    const int smem_bytes = (int)sizeof(SmemLayout);
    static int configured = 0;
    if (!configured) {
        cudaFuncSetAttribute(rcnn_sampler_kernel,
                             cudaFuncAttributeMaxDynamicSharedMemorySize, smem_bytes);
        configured = 1;
    }
    rcnn_sampler_kernel<<<GRID_PAD, NT, smem_bytes>>>(rois, scores, gt, rnd, out);
}